// round 6
// baseline (speedup 1.0000x reference)
#include <cuda_runtime.h>
#include <math.h>

#define H 512
#define W 512
#define NS 14            // number of gaussian scales (K+1)
#define NK 13            // number of DoG planes (K)
#define MAXR 43
#define NROWS (NK*H)
#define THRESH 0.001f
#define MAXPEAKS 32768

// ---- scratch (static device memory; no allocations allowed) ----
__device__ float2 d_tmp[NS*H*W];      // after horizontal blur (df64 hi/lo)
__device__ float  d_g[NS*H*W];        // gaussian pyramid, fp32 (matches ref's g)
__device__ float  d_dog[NK*H*W];      // DoG * sigma (fp32, from fp32 g like ref)
__device__ float2 d_k1d[NS*96];       // 1D kernels as df64 pairs (zero padded)
__device__ int    d_rad[NS];
__device__ float  d_sig[NS];
__device__ unsigned d_maskw[NROWS*16];// 512-bit peak mask per (k,y) row
__device__ int    d_rowcnt[NROWS];    // counts, then exclusive offsets

// ---- packed f32x2 helpers (Blackwell sm_100+ packed-float ops) ----
typedef unsigned long long u64t;
__device__ __forceinline__ u64t f2pack(float a, float b) {
    u64t r; asm("mov.b64 %0, {%1, %2};" : "=l"(r) : "f"(a), "f"(b)); return r;
}
__device__ __forceinline__ void f2unpack(u64t v, float& a, float& b) {
    asm("mov.b64 {%0, %1}, %2;" : "=f"(a), "=f"(b) : "l"(v));
}
__device__ __forceinline__ u64t f2mul(u64t a, u64t b) {
    u64t r; asm("mul.rn.f32x2 %0, %1, %2;" : "=l"(r) : "l"(a), "l"(b)); return r;
}
__device__ __forceinline__ u64t f2add(u64t a, u64t b) {
    u64t r; asm("add.rn.f32x2 %0, %1, %2;" : "=l"(r) : "l"(a), "l"(b)); return r;
}
__device__ __forceinline__ u64t f2sub(u64t a, u64t b) {
    u64t r; asm("sub.rn.f32x2 %0, %1, %2;" : "=l"(r) : "l"(a), "l"(b)); return r;
}
__device__ __forceinline__ u64t f2fma(u64t a, u64t b, u64t c) {
    u64t r; asm("fma.rn.f32x2 %0, %1, %2, %3;" : "=l"(r) : "l"(a), "l"(b), "l"(c)); return r;
}

// ---------------------------------------------------------------
// Build normalized 1D gaussian kernels in fp64, split to df64 pairs.
// ---------------------------------------------------------------
__global__ void build_kernels_k(const float* __restrict__ sigma_list) {
    int i   = blockIdx.x;
    int tid = threadIdx.x;      // 128 threads
    float sf = sigma_list[i];
    double s = (double)sf;
    int r   = (int)floor(4.0 * s + 0.5);   // TRUNCATE=4
    int n   = 2 * r + 1;
    __shared__ double tmp[96];
    __shared__ double ssum;
    if (tid < n) {
        double mean = 0.5 * (double)(n - 1);
        double d = ((double)tid - mean) / (2.0 * s);
        tmp[tid] = exp(-(d * d));
    }
    __syncthreads();
    if (tid == 0) {
        double acc = 0.0;
        for (int j = 0; j < n; j++) acc += tmp[j];
        ssum = acc;
        d_rad[i] = r;
        d_sig[i] = sf;
    }
    __syncthreads();
    if (tid < 96) {
        double v = (tid < n) ? tmp[tid] / ssum : 0.0;
        float vh = (float)v;
        float vl = (float)(v - (double)vh);
        d_k1d[i*96 + tid] = make_float2(vh, vl);
    }
}

// ---------------------------------------------------------------
// Horizontal pass. df64 via exact-product split + ANCHORED Fast2Sum,
// two outputs per packed f32x2 lane pair (4 outputs/thread).
// Negations folded: epn accumulates the NEGATED compensation via
// pre-negated coefficients (fma(a,-k,p) == -fma(a,k,-p) exactly),
// merged with one sub. Per-lane arithmetic == scalar df64 scheme.
// blockDim 128, grid (H, NS).
// ---------------------------------------------------------------
__global__ void hblur_k(const float* __restrict__ x) {
    int y  = blockIdx.x;
    int sc = blockIdx.y;
    int r  = d_rad[sc];
    int n  = 2 * r + 1;
    __shared__ float srow[W + 2*MAXR + 4];
    __shared__ u64t  skxx[96], snkxx[96], snkyy[96];
    int tid = threadIdx.x;
    for (int i = tid; i < W + 2*r; i += 128) {
        int xx = i - r;
        srow[i] = (xx >= 0 && xx < W) ? x[y*W + xx] : 0.f;
    }
    for (int i = tid; i < n; i += 128) {
        float2 k = d_k1d[sc*96 + i];
        skxx[i]  = f2pack(k.x, k.x);
        snkxx[i] = f2pack(-k.x, -k.x);
        snkyy[i] = f2pack(-k.y, -k.y);
    }
    __syncthreads();

    int xo = tid * 4;
    float wv0 = srow[xo], wv1 = srow[xo+1], wv2 = srow[xo+2], wv3 = srow[xo+3];
    u64t hi01 = f2pack(2.f, 2.f), lo01 = f2pack(0.f, 0.f);
    u64t hi23 = hi01,              lo23 = lo01;

    #pragma unroll 2
    for (int d = 0; d < n; d++) {
        u64t kxx = skxx[d], nkxx = snkxx[d], nkyy = snkyy[d];
        u64t a01 = f2pack(wv0, wv1);
        u64t a23 = f2pack(wv2, wv3);
        // pair (0,1)
        {
            u64t p   = f2mul(a01, kxx);
            u64t epn = f2fma(a01, nkxx, p);      // -(a*kx - p)
            epn      = f2fma(a01, nkyy, epn);    // -(a*ky + prev)
            u64t t   = f2add(hi01, p);           // Fast2Sum (hi >= 2 > p)
            u64t u   = f2sub(t, hi01);
            u64t e   = f2sub(p, u);
            u64t s2  = f2sub(e, epn);            // e + ep
            lo01 = f2add(lo01, s2);
            hi01 = t;
        }
        // pair (2,3)
        {
            u64t p   = f2mul(a23, kxx);
            u64t epn = f2fma(a23, nkxx, p);
            epn      = f2fma(a23, nkyy, epn);
            u64t t   = f2add(hi23, p);
            u64t u   = f2sub(t, hi23);
            u64t e   = f2sub(p, u);
            u64t s2  = f2sub(e, epn);
            lo23 = f2add(lo23, s2);
            hi23 = t;
        }
        wv0 = wv1; wv1 = wv2; wv2 = wv3;
        wv3 = srow[xo + d + 4];
    }
    u64t anchor = f2pack(2.f, 2.f);
    float h0, h1, h2, h3, l0, l1, l2, l3;
    f2unpack(f2sub(hi01, anchor), h0, h1);
    f2unpack(f2sub(hi23, anchor), h2, h3);
    f2unpack(lo01, l0, l1);
    f2unpack(lo23, l2, l3);
    float2* outp = d_tmp + (size_t)(sc*H + y) * W + xo;
    outp[0] = make_float2(h0, l0);
    outp[1] = make_float2(h1, l1);
    outp[2] = make_float2(h2, l2);
    outp[3] = make_float2(h3, l3);
}

// ---------------------------------------------------------------
// Vertical pass: 32-wide x-strip, 32 output rows/block, 4 per thread,
// packed f32x2 pairs; inputs are df64 pairs (hi,lo).
// blockDim (32,8), grid (16,16,NS).
// ---------------------------------------------------------------
#define VTX 32
#define VTY 32
__global__ void vblur_k() {
    int sc = blockIdx.z;
    int x0 = blockIdx.x * VTX;
    int y0 = blockIdx.y * VTY;
    int r  = d_rad[sc];
    int n  = 2 * r + 1;
    __shared__ float2 tile[(VTY + 2*MAXR + 2) * VTX];
    __shared__ u64t   skxx[96], snkxx[96], snkyy[96];
    int tx  = threadIdx.x;
    int tid = tx + threadIdx.y * VTX;   // 256 threads
    int rows = VTY + 2 * r;
    const float2* inp = d_tmp + (size_t)sc * H * W;
    for (int i = tid; i < rows * VTX; i += 256) {
        int rr = i / VTX, cc = i % VTX;
        int gy = y0 - r + rr;
        tile[i] = (gy >= 0 && gy < H) ? inp[gy*W + x0 + cc] : make_float2(0.f, 0.f);
    }
    for (int i = tid; i < n; i += 256) {
        float2 k = d_k1d[sc*96 + i];
        skxx[i]  = f2pack(k.x, k.x);
        snkxx[i] = f2pack(-k.x, -k.x);
        snkyy[i] = f2pack(-k.y, -k.y);
    }
    __syncthreads();

    int yo = threadIdx.y * 4;
    float2 wv0 = tile[(yo+0)*VTX + tx];
    float2 wv1 = tile[(yo+1)*VTX + tx];
    float2 wv2 = tile[(yo+2)*VTX + tx];
    float2 wv3 = tile[(yo+3)*VTX + tx];
    u64t hi01 = f2pack(2.f, 2.f), lo01 = f2pack(0.f, 0.f);
    u64t hi23 = hi01,              lo23 = lo01;

    #pragma unroll 2
    for (int d = 0; d < n; d++) {
        u64t kxx = skxx[d], nkxx = snkxx[d], nkyy = snkyy[d];
        u64t ax01 = f2pack(wv0.x, wv1.x);
        u64t ay01 = f2pack(wv0.y, wv1.y);
        u64t ax23 = f2pack(wv2.x, wv3.x);
        u64t ay23 = f2pack(wv2.y, wv3.y);
        // pair (0,1): mirrors scalar order (kx residual, ky term, lo-part term)
        {
            u64t p   = f2mul(ax01, kxx);
            u64t epn = f2fma(ax01, nkxx, p);
            epn      = f2fma(ax01, nkyy, epn);
            epn      = f2fma(ay01, nkxx, epn);
            u64t t   = f2add(hi01, p);
            u64t u   = f2sub(t, hi01);
            u64t e   = f2sub(p, u);
            u64t s2  = f2sub(e, epn);
            lo01 = f2add(lo01, s2);
            hi01 = t;
        }
        // pair (2,3)
        {
            u64t p   = f2mul(ax23, kxx);
            u64t epn = f2fma(ax23, nkxx, p);
            epn      = f2fma(ax23, nkyy, epn);
            epn      = f2fma(ay23, nkxx, epn);
            u64t t   = f2add(hi23, p);
            u64t u   = f2sub(t, hi23);
            u64t e   = f2sub(p, u);
            u64t s2  = f2sub(e, epn);
            lo23 = f2add(lo23, s2);
            hi23 = t;
        }
        wv0 = wv1; wv1 = wv2; wv2 = wv3;
        wv3 = tile[(yo + d + 4)*VTX + tx];
    }
    u64t anchor = f2pack(2.f, 2.f);
    u64t g01 = f2add(f2sub(hi01, anchor), lo01);   // (hi-2)+lo per lane
    u64t g23 = f2add(f2sub(hi23, anchor), lo23);
    float g0, g1, g2, g3;
    f2unpack(g01, g0, g1);
    f2unpack(g23, g2, g3);
    float* outp = d_g + (size_t)sc * H * W;
    outp[(y0 + yo + 0)*W + x0 + tx] = g0;
    outp[(y0 + yo + 1)*W + x0 + tx] = g1;
    outp[(y0 + yo + 2)*W + x0 + tx] = g2;
    outp[(y0 + yo + 3)*W + x0 + tx] = g3;
}

// ---------------------------------------------------------------
// DoG in fp32 (float4 vectorized): dog[k] = (g[k]-g[k+1])*sigma[k]
// ---------------------------------------------------------------
__global__ void dog_k() {
    int idx = blockIdx.x * blockDim.x + threadIdx.x;
    const int total4 = NK * H * W / 4;
    if (idx < total4) {
        int k = idx / (H * W / 4);
        float4 a = ((const float4*)d_g)[idx];
        float4 b = ((const float4*)d_g)[idx + H*W/4];
        float s = d_sig[k];
        float4 o;
        o.x = (a.x - b.x) * s;
        o.y = (a.y - b.y) * s;
        o.z = (a.z - b.z) * s;
        o.w = (a.w - b.w) * s;
        ((float4*)d_dog)[idx] = o;
    }
}

// ---------------------------------------------------------------
// Peak test: center > THRESH and >= all 26 neighbors.
// Border-excluded: k in [1,11], y,x in [1,510]. Ballot -> bit mask.
// ---------------------------------------------------------------
__global__ void peak_k() {
    int k    = blockIdx.z;
    int y    = blockIdx.y * 8 + threadIdx.y;
    int xw   = blockIdx.x;
    int lane = threadIdx.x;
    int x    = xw * 32 + lane;
    bool p = false;
    if (k >= 1 && k <= NK-2 && y >= 1 && y <= H-2 && x >= 1 && x <= W-2) {
        float c = d_dog[(k*H + y)*W + x];
        if (c > THRESH) {
            p = true;
            #pragma unroll
            for (int dk = -1; dk <= 1 && p; dk++)
                #pragma unroll
                for (int dy = -1; dy <= 1 && p; dy++)
                    #pragma unroll
                    for (int dx = -1; dx <= 1; dx++) {
                        if ((dk | dy | dx) == 0) continue;
                        if (d_dog[((k+dk)*H + (y+dy))*W + (x+dx)] > c) { p = false; break; }
                    }
        }
    }
    unsigned wmask = __ballot_sync(0xFFFFFFFFu, p);
    if (lane == 0) d_maskw[(k*H + y)*16 + xw] = wmask;
}

__global__ void rowcnt_k() {
    int rid = blockIdx.x * blockDim.x + threadIdx.x;
    if (rid < NROWS) {
        int c = 0;
        #pragma unroll
        for (int w = 0; w < 16; w++) c += __popc(d_maskw[rid*16 + w]);
        d_rowcnt[rid] = c;
    }
}

__global__ void scan_k() {
    const int PER = (NROWS + 1023) / 1024;   // 7
    int tid = threadIdx.x;
    int vals[PER];
    int local = 0;
    int start = tid * PER;
    #pragma unroll
    for (int j = 0; j < PER; j++) {
        int idx = start + j;
        int v = (idx < NROWS) ? d_rowcnt[idx] : 0;
        vals[j] = v;
        local += v;
    }
    __shared__ int sh[1024];
    sh[tid] = local;
    __syncthreads();
    for (int off = 1; off < 1024; off <<= 1) {
        int v = (tid >= off) ? sh[tid - off] : 0;
        __syncthreads();
        sh[tid] += v;
        __syncthreads();
    }
    int run = sh[tid] - local;
    #pragma unroll
    for (int j = 0; j < PER; j++) {
        int idx = start + j;
        if (idx < NROWS) { d_rowcnt[idx] = run; run += vals[j]; }
    }
}

__global__ void fill_k(float* __restrict__ out) {
    int i = blockIdx.x * blockDim.x + threadIdx.x;
    if (i < MAXPEAKS) {
        out[3*i]     = d_sig[0];
        out[3*i + 1] = 0.f;
        out[3*i + 2] = 0.f;
    }
}

__global__ void write_k(float* __restrict__ out) {
    int rid  = blockIdx.x;
    int lane = threadIdx.x;
    int k = rid >> 9, y = rid & 511;
    int run = d_rowcnt[rid];
    float sg = d_sig[k];
    for (int w = 0; w < 16; w++) {
        unsigned word = d_maskw[rid*16 + w];
        if (word) {
            if ((word >> lane) & 1u) {
                int idx = run + __popc(word & ((1u << lane) - 1u));
                if (idx < MAXPEAKS) {
                    out[3*idx]     = sg;
                    out[3*idx + 1] = (float)y;
                    out[3*idx + 2] = (float)(w*32 + lane);
                }
            }
            run += __popc(word);
        }
    }
}

extern "C" void kernel_launch(void* const* d_in, const int* in_sizes, int n_in,
                              void* d_out, int out_size) {
    const float* x     = nullptr;
    const float* sigma = nullptr;
    for (int i = 0; i < n_in; i++) {
        if (in_sizes[i] == H * W)   x     = (const float*)d_in[i];
        else if (in_sizes[i] == NS) sigma = (const float*)d_in[i];
    }
    if (!x)     x     = (const float*)d_in[0];
    if (!sigma) sigma = (const float*)d_in[n_in - 1];

    float* out = (float*)d_out;                   // [32768, 3]

    build_kernels_k<<<NS, 128>>>(sigma);
    hblur_k<<<dim3(H, NS), 128>>>(x);
    vblur_k<<<dim3(W/VTX, H/VTY, NS), dim3(VTX, 8)>>>();
    dog_k<<<(NK*H*W/4 + 255)/256, 256>>>();
    peak_k<<<dim3(16, H/8, NK), dim3(32, 8)>>>();
    rowcnt_k<<<(NROWS + 255)/256, 256>>>();
    scan_k<<<1, 1024>>>();
    fill_k<<<(MAXPEAKS + 255)/256, 256>>>(out);
    write_k<<<NROWS, 32>>>(out);
}

// round 7
// speedup vs baseline: 1.0886x; 1.0886x over previous
#include <cuda_runtime.h>
#include <math.h>

#define H 512
#define W 512
#define NS 14            // number of gaussian scales (K+1)
#define NK 13            // number of DoG planes (K)
#define MAXR 43
#define NROWS (NK*H)
#define THRESH 0.001f
#define MAXPEAKS 32768

// ---- scratch (static device memory; no allocations allowed) ----
__device__ float2 d_tmp[NS*H*W];      // after horizontal blur (df64 hi/lo)
__device__ float  d_g[NS*H*W];        // gaussian pyramid, fp32 (matches ref's g)
__device__ float  d_dog[NK*H*W];      // DoG * sigma (fp32, from fp32 g like ref)
__device__ float  d_kx[NS*96];        // 1D kernels, fp32-rounded coeffs (padded)
__device__ int    d_rad[NS];
__device__ float  d_sig[NS];
__device__ unsigned d_maskw[NROWS*16];// 512-bit peak mask per (k,y) row
__device__ int    d_rowcnt[NROWS];    // exclusive offsets after scan
__device__ int    d_total;            // total peak count

// ---------------------------------------------------------------
// Build normalized 1D gaussian kernels in fp64, round to fp32.
// (Coefficient fp32-rounding perturbs conv by <= 2^-24 relative,
// smooth/correlated across pixels -> decision-safe.)
// ---------------------------------------------------------------
__global__ void build_kernels_k(const float* __restrict__ sigma_list) {
    int i   = blockIdx.x;
    int tid = threadIdx.x;      // 128 threads
    float sf = sigma_list[i];
    double s = (double)sf;
    int r   = (int)floor(4.0 * s + 0.5);   // TRUNCATE=4
    int n   = 2 * r + 1;
    __shared__ double tmp[96];
    __shared__ double ssum;
    if (tid < n) {
        double mean = 0.5 * (double)(n - 1);
        double d = ((double)tid - mean) / (2.0 * s);
        tmp[tid] = exp(-(d * d));
    }
    __syncthreads();
    if (tid == 0) {
        double acc = 0.0;
        for (int j = 0; j < n; j++) acc += tmp[j];
        ssum = acc;
        d_rad[i] = r;
        d_sig[i] = sf;
    }
    __syncthreads();
    if (tid < 96) d_kx[i*96 + tid] = (tid < n) ? (float)(tmp[tid] / ssum) : 0.f;
}

// ---------------------------------------------------------------
// Horizontal pass. Exact-product split + ANCHORED Fast2Sum:
// all products p>=0 and sum(p)<1; hi seeded to 2.0 so hi>=2>p always
// -> 3-op error extraction exact; final (hi-2) exact (Sterbenz).
// 7 fma-pipe ops per tap. 4 outputs/thread, sliding register window.
// blockDim 128, grid (H, NS).
// ---------------------------------------------------------------
__global__ void hblur_k(const float* __restrict__ x) {
    int y  = blockIdx.x;
    int sc = blockIdx.y;
    int r  = d_rad[sc];
    int n  = 2 * r + 1;
    __shared__ float srow[W + 2*MAXR + 4];
    __shared__ float sk[96];
    int tid = threadIdx.x;
    for (int i = tid; i < W + 2*r; i += 128) {
        int xx = i - r;
        srow[i] = (xx >= 0 && xx < W) ? x[y*W + xx] : 0.f;
    }
    for (int i = tid; i < n; i += 128) sk[i] = d_kx[sc*96 + i];
    __syncthreads();

    int xo = tid * 4;
    float wv[4];
    #pragma unroll
    for (int j = 0; j < 4; j++) wv[j] = srow[xo + j];
    float hi[4] = {2.f, 2.f, 2.f, 2.f};
    float lo[4] = {0.f, 0.f, 0.f, 0.f};

    #pragma unroll 4
    for (int d = 0; d < n; d++) {
        float k = sk[d];
        #pragma unroll
        for (int j = 0; j < 4; j++) {
            float a  = wv[j];
            float p  = __fmul_rn(a, k);
            float ep = __fmaf_rn(a, k, -p);       // exact product residual
            float t  = __fadd_rn(hi[j], p);       // Fast2Sum (hi >= 2 > p)
            float e  = __fsub_rn(p, __fsub_rn(t, hi[j]));
            hi[j] = t;
            lo[j] = __fadd_rn(lo[j], e);
            lo[j] = __fadd_rn(lo[j], ep);
        }
        wv[0] = wv[1]; wv[1] = wv[2]; wv[2] = wv[3];
        wv[3] = srow[xo + d + 4];
    }
    float2* outp = d_tmp + (size_t)(sc*H + y) * W + xo;
    #pragma unroll
    for (int j = 0; j < 4; j++)
        outp[j] = make_float2(__fsub_rn(hi[j], 2.f), lo[j]);
}

// ---------------------------------------------------------------
// Vertical pass: 32-wide x-strip, 32 output rows/block, 4 per thread.
// Inputs are df64 pairs; 8 fma-pipe ops per tap.
// blockDim (32,8), grid (16,16,NS).
// ---------------------------------------------------------------
#define VTX 32
#define VTY 32
__global__ void vblur_k() {
    int sc = blockIdx.z;
    int x0 = blockIdx.x * VTX;
    int y0 = blockIdx.y * VTY;
    int r  = d_rad[sc];
    int n  = 2 * r + 1;
    __shared__ float2 tile[(VTY + 2*MAXR + 2) * VTX];
    __shared__ float  sk[96];
    int tx  = threadIdx.x;
    int tid = tx + threadIdx.y * VTX;   // 256 threads
    int rows = VTY + 2 * r;
    const float2* inp = d_tmp + (size_t)sc * H * W;
    for (int i = tid; i < rows * VTX; i += 256) {
        int rr = i / VTX, cc = i % VTX;
        int gy = y0 - r + rr;
        tile[i] = (gy >= 0 && gy < H) ? inp[gy*W + x0 + cc] : make_float2(0.f, 0.f);
    }
    for (int i = tid; i < n; i += 256) sk[i] = d_kx[sc*96 + i];
    __syncthreads();

    int yo = threadIdx.y * 4;
    float2 wv[4];
    #pragma unroll
    for (int j = 0; j < 4; j++) wv[j] = tile[(yo + j)*VTX + tx];
    float hi[4] = {2.f, 2.f, 2.f, 2.f};
    float lo[4] = {0.f, 0.f, 0.f, 0.f};

    #pragma unroll 4
    for (int d = 0; d < n; d++) {
        float k = sk[d];
        #pragma unroll
        for (int j = 0; j < 4; j++) {
            float2 a = wv[j];
            float p  = __fmul_rn(a.x, k);
            float ep = __fmaf_rn(a.x, k, -p);
            ep = __fmaf_rn(a.y, k, ep);
            float t  = __fadd_rn(hi[j], p);
            float e  = __fsub_rn(p, __fsub_rn(t, hi[j]));
            hi[j] = t;
            lo[j] = __fadd_rn(lo[j], e);
            lo[j] = __fadd_rn(lo[j], ep);
        }
        wv[0] = wv[1]; wv[1] = wv[2]; wv[2] = wv[3];
        wv[3] = tile[(yo + d + 4)*VTX + tx];
    }
    float* outp = d_g + (size_t)sc * H * W;
    #pragma unroll
    for (int j = 0; j < 4; j++)
        outp[(y0 + yo + j)*W + x0 + tx] =
            __fadd_rn(__fsub_rn(hi[j], 2.f), lo[j]);
}

// ---------------------------------------------------------------
// DoG in fp32 (float4 vectorized): dog[k] = (g[k]-g[k+1])*sigma[k]
// ---------------------------------------------------------------
__global__ void dog_k() {
    int idx = blockIdx.x * blockDim.x + threadIdx.x;
    const int total4 = NK * H * W / 4;
    if (idx < total4) {
        int k = idx / (H * W / 4);
        float4 a = ((const float4*)d_g)[idx];
        float4 b = ((const float4*)d_g)[idx + H*W/4];
        float s = d_sig[k];
        float4 o;
        o.x = (a.x - b.x) * s;
        o.y = (a.y - b.y) * s;
        o.z = (a.z - b.z) * s;
        o.w = (a.w - b.w) * s;
        ((float4*)d_dog)[idx] = o;
    }
}

// ---------------------------------------------------------------
// Peak test: center > THRESH and >= all 26 neighbors.
// Border-excluded: k in [1,11], y,x in [1,510]. Ballot -> bit mask.
// ---------------------------------------------------------------
__global__ void peak_k() {
    int k    = blockIdx.z;
    int y    = blockIdx.y * 8 + threadIdx.y;
    int xw   = blockIdx.x;
    int lane = threadIdx.x;
    int x    = xw * 32 + lane;
    bool p = false;
    if (k >= 1 && k <= NK-2 && y >= 1 && y <= H-2 && x >= 1 && x <= W-2) {
        float c = d_dog[(k*H + y)*W + x];
        if (c > THRESH) {
            p = true;
            #pragma unroll
            for (int dk = -1; dk <= 1 && p; dk++)
                #pragma unroll
                for (int dy = -1; dy <= 1 && p; dy++)
                    #pragma unroll
                    for (int dx = -1; dx <= 1; dx++) {
                        if ((dk | dy | dx) == 0) continue;
                        if (d_dog[((k+dk)*H + (y+dy))*W + (x+dx)] > c) { p = false; break; }
                    }
        }
    }
    unsigned wmask = __ballot_sync(0xFFFFFFFFu, p);
    if (lane == 0) d_maskw[(k*H + y)*16 + xw] = wmask;
}

// ---------------------------------------------------------------
// Fused count+scan: single block computes per-row popcounts from the
// masks and an exclusive scan over 6656 rows (row-major order).
// ---------------------------------------------------------------
__global__ void scan_k() {
    const int PER = (NROWS + 1023) / 1024;   // 7
    int tid = threadIdx.x;
    int vals[PER];
    int local = 0;
    int start = tid * PER;
    #pragma unroll
    for (int j = 0; j < PER; j++) {
        int idx = start + j;
        int v = 0;
        if (idx < NROWS) {
            const uint4* mw = (const uint4*)(d_maskw + idx*16);
            #pragma unroll
            for (int q = 0; q < 4; q++) {
                uint4 m = mw[q];
                v += __popc(m.x) + __popc(m.y) + __popc(m.z) + __popc(m.w);
            }
        }
        vals[j] = v;
        local += v;
    }
    __shared__ int sh[1024];
    sh[tid] = local;
    __syncthreads();
    for (int off = 1; off < 1024; off <<= 1) {
        int v = (tid >= off) ? sh[tid - off] : 0;
        __syncthreads();
        sh[tid] += v;
        __syncthreads();
    }
    int run = sh[tid] - local;
    #pragma unroll
    for (int j = 0; j < PER; j++) {
        int idx = start + j;
        if (idx < NROWS) { d_rowcnt[idx] = run; run += vals[j]; }
    }
    if (tid == 1023) d_total = sh[1023];
}

// ---------------------------------------------------------------
// Fused fill + scatter. Scatter writes rows [0, min(total,MAXPEAKS));
// fill writes rows [total, MAXPEAKS) -> disjoint, order-independent.
// grid NROWS blocks of 32 threads.
// ---------------------------------------------------------------
__global__ void write_k(float* __restrict__ out) {
    int rid  = blockIdx.x;
    int lane = threadIdx.x;
    int total = d_total;
    float sig0 = d_sig[0];
    // fill part: rows rid, rid+NROWS, ... that are >= total
    #pragma unroll
    for (int j = 0; j < 5; j++) {          // 5*NROWS = 33280 >= MAXPEAKS
        int f = rid + j * NROWS;
        if (f < MAXPEAKS && f >= total && lane < 3)
            out[3*f + lane] = (lane == 0) ? sig0 : 0.f;
    }
    // scatter part
    int k = rid >> 9, y = rid & 511;
    int run = d_rowcnt[rid];
    float sg = d_sig[k];
    for (int w = 0; w < 16; w++) {
        unsigned word = d_maskw[rid*16 + w];
        if (word) {
            if ((word >> lane) & 1u) {
                int idx = run + __popc(word & ((1u << lane) - 1u));
                if (idx < MAXPEAKS) {
                    out[3*idx]     = sg;
                    out[3*idx + 1] = (float)y;
                    out[3*idx + 2] = (float)(w*32 + lane);
                }
            }
            run += __popc(word);
        }
    }
}

extern "C" void kernel_launch(void* const* d_in, const int* in_sizes, int n_in,
                              void* d_out, int out_size) {
    const float* x     = nullptr;
    const float* sigma = nullptr;
    for (int i = 0; i < n_in; i++) {
        if (in_sizes[i] == H * W)   x     = (const float*)d_in[i];
        else if (in_sizes[i] == NS) sigma = (const float*)d_in[i];
    }
    if (!x)     x     = (const float*)d_in[0];
    if (!sigma) sigma = (const float*)d_in[n_in - 1];

    float* out = (float*)d_out;                   // [32768, 3]

    build_kernels_k<<<NS, 128>>>(sigma);
    hblur_k<<<dim3(H, NS), 128>>>(x);
    vblur_k<<<dim3(W/VTX, H/VTY, NS), dim3(VTX, 8)>>>();
    dog_k<<<(NK*H*W/4 + 255)/256, 256>>>();
    peak_k<<<dim3(16, H/8, NK), dim3(32, 8)>>>();
    scan_k<<<1, 1024>>>();
    write_k<<<NROWS, 32>>>(out);
}

// round 8
// speedup vs baseline: 1.2407x; 1.1397x over previous
#include <cuda_runtime.h>
#include <math.h>

#define H 512
#define W 512
#define NS 14            // number of gaussian scales (K+1)
#define NK 13            // number of DoG planes (K)
#define MAXR 43
#define NROWS (NK*H)
#define THRESH 0.001f
#define MAXPEAKS 32768

// ---- scratch (static device memory; no allocations allowed) ----
__device__ float2 d_tmp[NS*H*W];      // after horizontal blur (df64 hi/lo)
__device__ float  d_g[NS*H*W];        // gaussian pyramid, fp32 (matches ref's g)
__device__ float  d_dog[NK*H*W];      // DoG * sigma (fp32, from fp32 g like ref)
__device__ float  d_kx[NS*96];        // 1D kernels, fp32-rounded coeffs (padded)
__device__ int    d_rad[NS];
__device__ float  d_sig[NS];
__device__ unsigned d_maskw[NROWS*16];// 512-bit peak mask per (k,y) row
__device__ int    d_rowcnt[NROWS];    // exclusive offsets after scan
__device__ int    d_total;            // total peak count

// ---------------------------------------------------------------
// Build normalized 1D gaussian kernels in fp64, round to fp32.
// ---------------------------------------------------------------
__global__ void build_kernels_k(const float* __restrict__ sigma_list) {
    int i   = blockIdx.x;
    int tid = threadIdx.x;      // 128 threads
    float sf = sigma_list[i];
    double s = (double)sf;
    int r   = (int)floor(4.0 * s + 0.5);   // TRUNCATE=4
    int n   = 2 * r + 1;
    __shared__ double tmp[96];
    __shared__ double ssum;
    if (tid < n) {
        double mean = 0.5 * (double)(n - 1);
        double d = ((double)tid - mean) / (2.0 * s);
        tmp[tid] = exp(-(d * d));
    }
    __syncthreads();
    if (tid == 0) {
        double acc = 0.0;
        for (int j = 0; j < n; j++) acc += tmp[j];
        ssum = acc;
        d_rad[i] = r;
        d_sig[i] = sf;
    }
    __syncthreads();
    if (tid < 96) d_kx[i*96 + tid] = (tid < n) ? (float)(tmp[tid] / ssum) : 0.f;
}

// ---------------------------------------------------------------
// Horizontal pass, SYMMETRIC pairing: (a_left + a_right) * k[j].
// Exact-product split + ANCHORED Fast2Sum (hi seeded 2.0: all pair
// products p in [0,0.2), sum<1 -> extraction exact; hi-2 exact).
// Two sliding register windows (fwd for left taps, bwd for right).
// 4 outputs/thread. blockDim 128, grid (H, NS).
// ---------------------------------------------------------------
__global__ void hblur_k(const float* __restrict__ x) {
    int y  = blockIdx.x;
    int sc = blockIdx.y;
    int r  = d_rad[sc];
    int n  = 2 * r + 1;
    __shared__ float srow[W + 2*MAXR + 8];
    __shared__ float sk[96];
    int tid = threadIdx.x;
    for (int i = tid; i < W + 2*r + 4; i += 128) {
        int xx = i - r;
        srow[i] = (xx >= 0 && xx < W) ? x[y*W + xx] : 0.f;
    }
    for (int i = tid; i < n; i += 128) sk[i] = d_kx[sc*96 + i];
    __syncthreads();

    int xo = tid * 4;
    float wl[4], wr[4];
    #pragma unroll
    for (int t = 0; t < 4; t++) {
        wl[t] = srow[xo + t];            // left taps, slides forward
        wr[t] = srow[xo + n - 1 + t];    // right taps, slides backward
    }
    float hi[4] = {2.f, 2.f, 2.f, 2.f};
    float lo[4] = {0.f, 0.f, 0.f, 0.f};

    #pragma unroll 2
    for (int j = 0; j < r; j++) {
        float k = sk[j];
        #pragma unroll
        for (int t = 0; t < 4; t++) {
            float s  = __fadd_rn(wl[t], wr[t]);   // only new rounding vs R7
            float p  = __fmul_rn(s, k);
            float ep = __fmaf_rn(s, k, -p);       // exact product residual
            float t2 = __fadd_rn(hi[t], p);       // Fast2Sum (hi >= 2 > p)
            float e  = __fsub_rn(p, __fsub_rn(t2, hi[t]));
            hi[t] = t2;
            lo[t] = __fadd_rn(lo[t], e);
            lo[t] = __fadd_rn(lo[t], ep);
        }
        wl[0] = wl[1]; wl[1] = wl[2]; wl[2] = wl[3];
        wl[3] = srow[xo + j + 4];
        wr[3] = wr[2]; wr[2] = wr[1]; wr[1] = wr[0];
        wr[0] = srow[xo + n - 2 - j];
    }
    // center tap: wl[t] == srow[xo + r + t] after r slides
    {
        float kc = sk[r];
        #pragma unroll
        for (int t = 0; t < 4; t++) {
            float a  = wl[t];
            float p  = __fmul_rn(a, kc);
            float ep = __fmaf_rn(a, kc, -p);
            float t2 = __fadd_rn(hi[t], p);
            float e  = __fsub_rn(p, __fsub_rn(t2, hi[t]));
            hi[t] = t2;
            lo[t] = __fadd_rn(lo[t], e);
            lo[t] = __fadd_rn(lo[t], ep);
        }
    }
    float2* outp = d_tmp + (size_t)(sc*H + y) * W + xo;
    #pragma unroll
    for (int t = 0; t < 4; t++)
        outp[t] = make_float2(__fsub_rn(hi[t], 2.f), lo[t]);
}

// ---------------------------------------------------------------
// Vertical pass, symmetric pairing on df64 inputs.
// 32-wide x-strip, 32 output rows/block, 4 per thread.
// blockDim (32,8), grid (16,16,NS).
// ---------------------------------------------------------------
#define VTX 32
#define VTY 32
__global__ void vblur_k() {
    int sc = blockIdx.z;
    int x0 = blockIdx.x * VTX;
    int y0 = blockIdx.y * VTY;
    int r  = d_rad[sc];
    int n  = 2 * r + 1;
    __shared__ float2 tile[(VTY + 2*MAXR + 4) * VTX];
    __shared__ float  sk[96];
    int tx  = threadIdx.x;
    int tid = tx + threadIdx.y * VTX;   // 256 threads
    int rows = VTY + 2 * r + 3;
    const float2* inp = d_tmp + (size_t)sc * H * W;
    for (int i = tid; i < rows * VTX; i += 256) {
        int rr = i / VTX, cc = i % VTX;
        int gy = y0 - r + rr;
        tile[i] = (gy >= 0 && gy < H) ? inp[gy*W + x0 + cc] : make_float2(0.f, 0.f);
    }
    for (int i = tid; i < n; i += 256) sk[i] = d_kx[sc*96 + i];
    __syncthreads();

    int yo = threadIdx.y * 4;
    float2 wl[4], wr[4];
    #pragma unroll
    for (int t = 0; t < 4; t++) {
        wl[t] = tile[(yo + t)*VTX + tx];
        wr[t] = tile[(yo + n - 1 + t)*VTX + tx];
    }
    float hi[4] = {2.f, 2.f, 2.f, 2.f};
    float lo[4] = {0.f, 0.f, 0.f, 0.f};

    #pragma unroll 2
    for (int j = 0; j < r; j++) {
        float k = sk[j];
        #pragma unroll
        for (int t = 0; t < 4; t++) {
            float sx = __fadd_rn(wl[t].x, wr[t].x);   // only new rounding
            float sy = __fadd_rn(wl[t].y, wr[t].y);
            float p  = __fmul_rn(sx, k);
            float ep = __fmaf_rn(sx, k, -p);
            ep = __fmaf_rn(sy, k, ep);
            float t2 = __fadd_rn(hi[t], p);
            float e  = __fsub_rn(p, __fsub_rn(t2, hi[t]));
            hi[t] = t2;
            lo[t] = __fadd_rn(lo[t], e);
            lo[t] = __fadd_rn(lo[t], ep);
        }
        wl[0] = wl[1]; wl[1] = wl[2]; wl[2] = wl[3];
        wl[3] = tile[(yo + j + 4)*VTX + tx];
        wr[3] = wr[2]; wr[2] = wr[1]; wr[1] = wr[0];
        wr[0] = tile[(yo + n - 2 - j)*VTX + tx];
    }
    // center tap
    {
        float kc = sk[r];
        #pragma unroll
        for (int t = 0; t < 4; t++) {
            float2 a = wl[t];
            float p  = __fmul_rn(a.x, kc);
            float ep = __fmaf_rn(a.x, kc, -p);
            ep = __fmaf_rn(a.y, kc, ep);
            float t2 = __fadd_rn(hi[t], p);
            float e  = __fsub_rn(p, __fsub_rn(t2, hi[t]));
            hi[t] = t2;
            lo[t] = __fadd_rn(lo[t], e);
            lo[t] = __fadd_rn(lo[t], ep);
        }
    }
    float* outp = d_g + (size_t)sc * H * W;
    #pragma unroll
    for (int t = 0; t < 4; t++)
        outp[(y0 + yo + t)*W + x0 + tx] =
            __fadd_rn(__fsub_rn(hi[t], 2.f), lo[t]);
}

// ---------------------------------------------------------------
// DoG in fp32 (float4 vectorized): dog[k] = (g[k]-g[k+1])*sigma[k]
// ---------------------------------------------------------------
__global__ void dog_k() {
    int idx = blockIdx.x * blockDim.x + threadIdx.x;
    const int total4 = NK * H * W / 4;
    if (idx < total4) {
        int k = idx / (H * W / 4);
        float4 a = ((const float4*)d_g)[idx];
        float4 b = ((const float4*)d_g)[idx + H*W/4];
        float s = d_sig[k];
        float4 o;
        o.x = (a.x - b.x) * s;
        o.y = (a.y - b.y) * s;
        o.z = (a.z - b.z) * s;
        o.w = (a.w - b.w) * s;
        ((float4*)d_dog)[idx] = o;
    }
}

// ---------------------------------------------------------------
// Peak test: center > THRESH and >= all 26 neighbors.
// Border-excluded: k in [1,11], y,x in [1,510]. Ballot -> bit mask.
// ---------------------------------------------------------------
__global__ void peak_k() {
    int k    = blockIdx.z;
    int y    = blockIdx.y * 8 + threadIdx.y;
    int xw   = blockIdx.x;
    int lane = threadIdx.x;
    int x    = xw * 32 + lane;
    bool p = false;
    if (k >= 1 && k <= NK-2 && y >= 1 && y <= H-2 && x >= 1 && x <= W-2) {
        float c = d_dog[(k*H + y)*W + x];
        if (c > THRESH) {
            p = true;
            #pragma unroll
            for (int dk = -1; dk <= 1 && p; dk++)
                #pragma unroll
                for (int dy = -1; dy <= 1 && p; dy++)
                    #pragma unroll
                    for (int dx = -1; dx <= 1; dx++) {
                        if ((dk | dy | dx) == 0) continue;
                        if (d_dog[((k+dk)*H + (y+dy))*W + (x+dx)] > c) { p = false; break; }
                    }
        }
    }
    unsigned wmask = __ballot_sync(0xFFFFFFFFu, p);
    if (lane == 0) d_maskw[(k*H + y)*16 + xw] = wmask;
}

// ---------------------------------------------------------------
// Fused count+scan over 6656 rows (row-major order), single block.
// ---------------------------------------------------------------
__global__ void scan_k() {
    const int PER = (NROWS + 1023) / 1024;   // 7
    int tid = threadIdx.x;
    int vals[PER];
    int local = 0;
    int start = tid * PER;
    #pragma unroll
    for (int j = 0; j < PER; j++) {
        int idx = start + j;
        int v = 0;
        if (idx < NROWS) {
            const uint4* mw = (const uint4*)(d_maskw + idx*16);
            #pragma unroll
            for (int q = 0; q < 4; q++) {
                uint4 m = mw[q];
                v += __popc(m.x) + __popc(m.y) + __popc(m.z) + __popc(m.w);
            }
        }
        vals[j] = v;
        local += v;
    }
    __shared__ int sh[1024];
    sh[tid] = local;
    __syncthreads();
    for (int off = 1; off < 1024; off <<= 1) {
        int v = (tid >= off) ? sh[tid - off] : 0;
        __syncthreads();
        sh[tid] += v;
        __syncthreads();
    }
    int run = sh[tid] - local;
    #pragma unroll
    for (int j = 0; j < PER; j++) {
        int idx = start + j;
        if (idx < NROWS) { d_rowcnt[idx] = run; run += vals[j]; }
    }
    if (tid == 1023) d_total = sh[1023];
}

// ---------------------------------------------------------------
// Fused fill + scatter (disjoint index ranges, order-independent).
// grid NROWS blocks of 32 threads.
// ---------------------------------------------------------------
__global__ void write_k(float* __restrict__ out) {
    int rid  = blockIdx.x;
    int lane = threadIdx.x;
    int total = d_total;
    float sig0 = d_sig[0];
    #pragma unroll
    for (int j = 0; j < 5; j++) {          // 5*NROWS = 33280 >= MAXPEAKS
        int f = rid + j * NROWS;
        if (f < MAXPEAKS && f >= total && lane < 3)
            out[3*f + lane] = (lane == 0) ? sig0 : 0.f;
    }
    int k = rid >> 9, y = rid & 511;
    int run = d_rowcnt[rid];
    float sg = d_sig[k];
    for (int w = 0; w < 16; w++) {
        unsigned word = d_maskw[rid*16 + w];
        if (word) {
            if ((word >> lane) & 1u) {
                int idx = run + __popc(word & ((1u << lane) - 1u));
                if (idx < MAXPEAKS) {
                    out[3*idx]     = sg;
                    out[3*idx + 1] = (float)y;
                    out[3*idx + 2] = (float)(w*32 + lane);
                }
            }
            run += __popc(word);
        }
    }
}

extern "C" void kernel_launch(void* const* d_in, const int* in_sizes, int n_in,
                              void* d_out, int out_size) {
    const float* x     = nullptr;
    const float* sigma = nullptr;
    for (int i = 0; i < n_in; i++) {
        if (in_sizes[i] == H * W)   x     = (const float*)d_in[i];
        else if (in_sizes[i] == NS) sigma = (const float*)d_in[i];
    }
    if (!x)     x     = (const float*)d_in[0];
    if (!sigma) sigma = (const float*)d_in[n_in - 1];

    float* out = (float*)d_out;                   // [32768, 3]

    build_kernels_k<<<NS, 128>>>(sigma);
    hblur_k<<<dim3(H, NS), 128>>>(x);
    vblur_k<<<dim3(W/VTX, H/VTY, NS), dim3(VTX, 8)>>>();
    dog_k<<<(NK*H*W/4 + 255)/256, 256>>>();
    peak_k<<<dim3(16, H/8, NK), dim3(32, 8)>>>();
    scan_k<<<1, 1024>>>();
    write_k<<<NROWS, 32>>>(out);
}

// round 9
// speedup vs baseline: 1.3093x; 1.0553x over previous
#include <cuda_runtime.h>
#include <math.h>

#define H 512
#define W 512
#define NS 14            // number of gaussian scales (K+1)
#define NK 13            // number of DoG planes (K)
#define MAXR 43
#define NROWS (NK*H)
#define THRESH 0.001f
#define MAXPEAKS 32768

// ---- scratch (static device memory; no allocations allowed) ----
__device__ float2 d_tmp[NS*H*W];      // after horizontal blur (df64 hi/lo)
__device__ float  d_g[NS*H*W];        // gaussian pyramid, fp32 (matches ref's g)
__device__ float  d_kx[NS*96];        // 1D kernels, fp32-rounded coeffs (padded)
__device__ int    d_rad[NS];
__device__ float  d_sig[NS];
__device__ unsigned d_maskw[NROWS*16];// 512-bit peak mask per (k,y) row
                                      // (k=0 and k=12 rows: never written, BSS zero)
__device__ int    d_rowcnt[NROWS];    // exclusive offsets after scan
__device__ int    d_total;            // total peak count

// ---------------------------------------------------------------
// Build normalized 1D gaussian kernels in fp64, round to fp32.
// ---------------------------------------------------------------
__global__ void build_kernels_k(const float* __restrict__ sigma_list) {
    int i   = blockIdx.x;
    int tid = threadIdx.x;      // 128 threads
    float sf = sigma_list[i];
    double s = (double)sf;
    int r   = (int)floor(4.0 * s + 0.5);   // TRUNCATE=4
    int n   = 2 * r + 1;
    __shared__ double tmp[96];
    __shared__ double ssum;
    if (tid < n) {
        double mean = 0.5 * (double)(n - 1);
        double d = ((double)tid - mean) / (2.0 * s);
        tmp[tid] = exp(-(d * d));
    }
    __syncthreads();
    if (tid == 0) {
        double acc = 0.0;
        for (int j = 0; j < n; j++) acc += tmp[j];
        ssum = acc;
        d_rad[i] = r;
        d_sig[i] = sf;
    }
    __syncthreads();
    if (tid < 96) d_kx[i*96 + tid] = (tid < n) ? (float)(tmp[tid] / ssum) : 0.f;
}

// ---------------------------------------------------------------
// Horizontal pass, SYMMETRIC pairing: (a_left + a_right) * k[j].
// Exact-product split + ANCHORED Fast2Sum (hi seeded 2.0).
// Unroll 4: window slides become register renaming (no MOVs).
// 4 outputs/thread. blockDim 128, grid (H, NS).
// ---------------------------------------------------------------
__global__ void hblur_k(const float* __restrict__ x) {
    int y  = blockIdx.x;
    int sc = blockIdx.y;
    int r  = d_rad[sc];
    int n  = 2 * r + 1;
    __shared__ float srow[W + 2*MAXR + 8];
    __shared__ float sk[96];
    int tid = threadIdx.x;
    for (int i = tid; i < W + 2*r + 4; i += 128) {
        int xx = i - r;
        srow[i] = (xx >= 0 && xx < W) ? x[y*W + xx] : 0.f;
    }
    for (int i = tid; i < n; i += 128) sk[i] = d_kx[sc*96 + i];
    __syncthreads();

    int xo = tid * 4;
    float wl[4], wr[4];
    #pragma unroll
    for (int t = 0; t < 4; t++) {
        wl[t] = srow[xo + t];            // left taps, slides forward
        wr[t] = srow[xo + n - 1 + t];    // right taps, slides backward
    }
    float hi[4] = {2.f, 2.f, 2.f, 2.f};
    float lo[4] = {0.f, 0.f, 0.f, 0.f};

    #pragma unroll 4
    for (int j = 0; j < r; j++) {
        float k = sk[j];
        #pragma unroll
        for (int t = 0; t < 4; t++) {
            float s  = __fadd_rn(wl[t], wr[t]);
            float p  = __fmul_rn(s, k);
            float ep = __fmaf_rn(s, k, -p);       // exact product residual
            float t2 = __fadd_rn(hi[t], p);       // Fast2Sum (hi >= 2 > p)
            float e  = __fsub_rn(p, __fsub_rn(t2, hi[t]));
            hi[t] = t2;
            lo[t] = __fadd_rn(lo[t], e);
            lo[t] = __fadd_rn(lo[t], ep);
        }
        wl[0] = wl[1]; wl[1] = wl[2]; wl[2] = wl[3];
        wl[3] = srow[xo + j + 4];
        wr[3] = wr[2]; wr[2] = wr[1]; wr[1] = wr[0];
        wr[0] = srow[xo + n - 2 - j];
    }
    // center tap: wl[t] == srow[xo + r + t] after r slides
    {
        float kc = sk[r];
        #pragma unroll
        for (int t = 0; t < 4; t++) {
            float a  = wl[t];
            float p  = __fmul_rn(a, kc);
            float ep = __fmaf_rn(a, kc, -p);
            float t2 = __fadd_rn(hi[t], p);
            float e  = __fsub_rn(p, __fsub_rn(t2, hi[t]));
            hi[t] = t2;
            lo[t] = __fadd_rn(lo[t], e);
            lo[t] = __fadd_rn(lo[t], ep);
        }
    }
    float2* outp = d_tmp + (size_t)(sc*H + y) * W + xo;
    #pragma unroll
    for (int t = 0; t < 4; t++)
        outp[t] = make_float2(__fsub_rn(hi[t], 2.f), lo[t]);
}

// ---------------------------------------------------------------
// Vertical pass, symmetric pairing on df64 inputs, unroll 4.
// 32-wide x-strip, 32 output rows/block, 4 per thread.
// blockDim (32,8), grid (16,16,NS).
// ---------------------------------------------------------------
#define VTX 32
#define VTY 32
__global__ void vblur_k() {
    int sc = blockIdx.z;
    int x0 = blockIdx.x * VTX;
    int y0 = blockIdx.y * VTY;
    int r  = d_rad[sc];
    int n  = 2 * r + 1;
    __shared__ float2 tile[(VTY + 2*MAXR + 4) * VTX];
    __shared__ float  sk[96];
    int tx  = threadIdx.x;
    int tid = tx + threadIdx.y * VTX;   // 256 threads
    int rows = VTY + 2 * r + 3;
    const float2* inp = d_tmp + (size_t)sc * H * W;
    for (int i = tid; i < rows * VTX; i += 256) {
        int rr = i / VTX, cc = i % VTX;
        int gy = y0 - r + rr;
        tile[i] = (gy >= 0 && gy < H) ? inp[gy*W + x0 + cc] : make_float2(0.f, 0.f);
    }
    for (int i = tid; i < n; i += 256) sk[i] = d_kx[sc*96 + i];
    __syncthreads();

    int yo = threadIdx.y * 4;
    float2 wl[4], wr[4];
    #pragma unroll
    for (int t = 0; t < 4; t++) {
        wl[t] = tile[(yo + t)*VTX + tx];
        wr[t] = tile[(yo + n - 1 + t)*VTX + tx];
    }
    float hi[4] = {2.f, 2.f, 2.f, 2.f};
    float lo[4] = {0.f, 0.f, 0.f, 0.f};

    #pragma unroll 4
    for (int j = 0; j < r; j++) {
        float k = sk[j];
        #pragma unroll
        for (int t = 0; t < 4; t++) {
            float sx = __fadd_rn(wl[t].x, wr[t].x);
            float sy = __fadd_rn(wl[t].y, wr[t].y);
            float p  = __fmul_rn(sx, k);
            float ep = __fmaf_rn(sx, k, -p);
            ep = __fmaf_rn(sy, k, ep);
            float t2 = __fadd_rn(hi[t], p);
            float e  = __fsub_rn(p, __fsub_rn(t2, hi[t]));
            hi[t] = t2;
            lo[t] = __fadd_rn(lo[t], e);
            lo[t] = __fadd_rn(lo[t], ep);
        }
        wl[0] = wl[1]; wl[1] = wl[2]; wl[2] = wl[3];
        wl[3] = tile[(yo + j + 4)*VTX + tx];
        wr[3] = wr[2]; wr[2] = wr[1]; wr[1] = wr[0];
        wr[0] = tile[(yo + n - 2 - j)*VTX + tx];
    }
    // center tap
    {
        float kc = sk[r];
        #pragma unroll
        for (int t = 0; t < 4; t++) {
            float2 a = wl[t];
            float p  = __fmul_rn(a.x, kc);
            float ep = __fmaf_rn(a.x, kc, -p);
            ep = __fmaf_rn(a.y, kc, ep);
            float t2 = __fadd_rn(hi[t], p);
            float e  = __fsub_rn(p, __fsub_rn(t2, hi[t]));
            hi[t] = t2;
            lo[t] = __fadd_rn(lo[t], e);
            lo[t] = __fadd_rn(lo[t], ep);
        }
    }
    float* outp = d_g + (size_t)sc * H * W;
    #pragma unroll
    for (int t = 0; t < 4; t++)
        outp[(y0 + yo + t)*W + x0 + tx] =
            __fadd_rn(__fsub_rn(hi[t], 2.f), lo[t]);
}

// ---------------------------------------------------------------
// FUSED DoG + peak test. Block covers (k, y0..y0+8, x0..x0+128) for
// k in [1, NK-2]. Loads g planes k-1..k+2, computes
// dog[k'] = (g[k']-g[k'+1])*sig[k'] (bit-identical to the unfused
// expression) into a 3x10x130 smem tile, then peak tests from LDS.
// Edge tile cells use clamped coords; they are only read as
// neighbors of border-excluded pixels, so their values are unused.
// blockDim (32,8), grid (4, 64, NK-2).
// ---------------------------------------------------------------
#define PTX 128
#define PTY 8
#define TCOLS (PTX + 2)
__global__ void peak_k() {
    int k  = blockIdx.z + 1;            // 1..11
    int y0 = blockIdx.y * PTY;
    int x0 = blockIdx.x * PTX;
    __shared__ float sdog[3][PTY + 2][TCOLS];
    int tx  = threadIdx.x;
    int tid = tx + threadIdx.y * 32;    // 256 threads

    // load + compute dog tile
    #pragma unroll
    for (int p = 0; p < 3; p++) {
        int kp = k - 1 + p;
        float sg = d_sig[kp];
        const float* g0 = d_g + (size_t)kp * H * W;
        const float* g1 = g0 + H * W;
        for (int i = tid; i < (PTY + 2) * TCOLS; i += 256) {
            int rr = i / TCOLS, cc = i % TCOLS;
            int gy = y0 - 1 + rr; if (gy < 0) gy = 0; if (gy > H-1) gy = H-1;
            int gx = x0 - 1 + cc; if (gx < 0) gx = 0; if (gx > W-1) gx = W-1;
            int gi = gy * W + gx;
            sdog[p][rr][cc] = (g0[gi] - g1[gi]) * sg;
        }
    }
    __syncthreads();

    int y  = y0 + threadIdx.y;
    int ly = threadIdx.y + 1;           // tile row of center
    #pragma unroll
    for (int q = 0; q < 4; q++) {
        int x  = x0 + q * 32 + tx;
        int lx = q * 32 + tx + 1;       // tile col of center
        bool pk = false;
        if (y >= 1 && y <= H-2 && x >= 1 && x <= W-2) {
            float c = sdog[1][ly][lx];
            if (c > THRESH) {
                pk = true;
                #pragma unroll
                for (int dk = 0; dk < 3 && pk; dk++)
                    #pragma unroll
                    for (int dy = -1; dy <= 1 && pk; dy++)
                        #pragma unroll
                        for (int dx = -1; dx <= 1; dx++) {
                            if (dk == 1 && dy == 0 && dx == 0) continue;
                            if (sdog[dk][ly+dy][lx+dx] > c) { pk = false; break; }
                        }
            }
        }
        unsigned wmask = __ballot_sync(0xFFFFFFFFu, pk);
        if (tx == 0) d_maskw[(k*H + y)*16 + (x0/32 + q)] = wmask;
    }
}

// ---------------------------------------------------------------
// Fused count+scan over 6656 rows (row-major order), single block.
// ---------------------------------------------------------------
__global__ void scan_k() {
    const int PER = (NROWS + 1023) / 1024;   // 7
    int tid = threadIdx.x;
    int vals[PER];
    int local = 0;
    int start = tid * PER;
    #pragma unroll
    for (int j = 0; j < PER; j++) {
        int idx = start + j;
        int v = 0;
        if (idx < NROWS) {
            const uint4* mw = (const uint4*)(d_maskw + idx*16);
            #pragma unroll
            for (int q = 0; q < 4; q++) {
                uint4 m = mw[q];
                v += __popc(m.x) + __popc(m.y) + __popc(m.z) + __popc(m.w);
            }
        }
        vals[j] = v;
        local += v;
    }
    __shared__ int sh[1024];
    sh[tid] = local;
    __syncthreads();
    for (int off = 1; off < 1024; off <<= 1) {
        int v = (tid >= off) ? sh[tid - off] : 0;
        __syncthreads();
        sh[tid] += v;
        __syncthreads();
    }
    int run = sh[tid] - local;
    #pragma unroll
    for (int j = 0; j < PER; j++) {
        int idx = start + j;
        if (idx < NROWS) { d_rowcnt[idx] = run; run += vals[j]; }
    }
    if (tid == 1023) d_total = sh[1023];
}

// ---------------------------------------------------------------
// Fused fill + scatter (disjoint index ranges, order-independent).
// grid NROWS blocks of 32 threads.
// ---------------------------------------------------------------
__global__ void write_k(float* __restrict__ out) {
    int rid  = blockIdx.x;
    int lane = threadIdx.x;
    int total = d_total;
    float sig0 = d_sig[0];
    #pragma unroll
    for (int j = 0; j < 5; j++) {          // 5*NROWS = 33280 >= MAXPEAKS
        int f = rid + j * NROWS;
        if (f < MAXPEAKS && f >= total && lane < 3)
            out[3*f + lane] = (lane == 0) ? sig0 : 0.f;
    }
    int k = rid >> 9, y = rid & 511;
    int run = d_rowcnt[rid];
    float sg = d_sig[k];
    for (int w = 0; w < 16; w++) {
        unsigned word = d_maskw[rid*16 + w];
        if (word) {
            if ((word >> lane) & 1u) {
                int idx = run + __popc(word & ((1u << lane) - 1u));
                if (idx < MAXPEAKS) {
                    out[3*idx]     = sg;
                    out[3*idx + 1] = (float)y;
                    out[3*idx + 2] = (float)(w*32 + lane);
                }
            }
            run += __popc(word);
        }
    }
}

extern "C" void kernel_launch(void* const* d_in, const int* in_sizes, int n_in,
                              void* d_out, int out_size) {
    const float* x     = nullptr;
    const float* sigma = nullptr;
    for (int i = 0; i < n_in; i++) {
        if (in_sizes[i] == H * W)   x     = (const float*)d_in[i];
        else if (in_sizes[i] == NS) sigma = (const float*)d_in[i];
    }
    if (!x)     x     = (const float*)d_in[0];
    if (!sigma) sigma = (const float*)d_in[n_in - 1];

    float* out = (float*)d_out;                   // [32768, 3]

    build_kernels_k<<<NS, 128>>>(sigma);
    hblur_k<<<dim3(H, NS), 128>>>(x);
    vblur_k<<<dim3(W/VTX, H/VTY, NS), dim3(VTX, 8)>>>();
    peak_k<<<dim3(W/PTX, H/PTY, NK-2), dim3(32, 8)>>>();
    scan_k<<<1, 1024>>>();
    write_k<<<NROWS, 32>>>(out);
}

// round 10
// speedup vs baseline: 1.3347x; 1.0194x over previous
#include <cuda_runtime.h>
#include <math.h>

#define H 512
#define W 512
#define NS 14            // number of gaussian scales (K+1)
#define NK 13            // number of DoG planes (K)
#define MAXR 43
#define NROWS (NK*H)
#define THRESH 0.001f
#define MAXPEAKS 32768

// ---- scratch (static device memory; no allocations allowed) ----
__device__ float2 d_tmp[NS*H*W];      // after horizontal blur (df64 hi/lo)
__device__ float  d_g[NS*H*W];        // gaussian pyramid, fp32 (matches ref's g)
__device__ float  d_kx[NS*96];        // 1D kernels, fp32-rounded coeffs (padded)
__device__ int    d_rad[NS];
__device__ float  d_sig[NS];
__device__ unsigned d_maskw[NROWS*16];// 512-bit peak mask per (k,y) row
                                      // (k=0 and k=12 rows: never written, BSS zero)
__device__ int    d_rowcnt[NROWS];    // exclusive offsets after scan
__device__ int    d_total;            // total peak count

// ---------------------------------------------------------------
// Build normalized 1D gaussian kernels in fp64, round to fp32.
// ---------------------------------------------------------------
__global__ void build_kernels_k(const float* __restrict__ sigma_list) {
    int i   = blockIdx.x;
    int tid = threadIdx.x;      // 128 threads
    float sf = sigma_list[i];
    double s = (double)sf;
    int r   = (int)floor(4.0 * s + 0.5);   // TRUNCATE=4
    int n   = 2 * r + 1;
    __shared__ double tmp[96];
    __shared__ double ssum;
    if (tid < n) {
        double mean = 0.5 * (double)(n - 1);
        double d = ((double)tid - mean) / (2.0 * s);
        tmp[tid] = exp(-(d * d));
    }
    __syncthreads();
    if (tid == 0) {
        double acc = 0.0;
        for (int j = 0; j < n; j++) acc += tmp[j];
        ssum = acc;
        d_rad[i] = r;
        d_sig[i] = sf;
    }
    __syncthreads();
    if (tid < 96) d_kx[i*96 + tid] = (tid < n) ? (float)(tmp[tid] / ssum) : 0.f;
}

// ---------------------------------------------------------------
// Horizontal pass, SYMMETRIC pairing: (a_left + a_right) * k[j].
// Exact-product split + ANCHORED Fast2Sum (hi seeded 2.0).
// 4 outputs/thread. blockDim 128, grid (H, NS).
// ---------------------------------------------------------------
__global__ void hblur_k(const float* __restrict__ x) {
    int y  = blockIdx.x;
    int sc = blockIdx.y;
    int r  = d_rad[sc];
    int n  = 2 * r + 1;
    __shared__ float srow[W + 2*MAXR + 8];
    __shared__ float sk[96];
    int tid = threadIdx.x;
    for (int i = tid; i < W + 2*r + 4; i += 128) {
        int xx = i - r;
        srow[i] = (xx >= 0 && xx < W) ? x[y*W + xx] : 0.f;
    }
    for (int i = tid; i < n; i += 128) sk[i] = d_kx[sc*96 + i];
    __syncthreads();

    int xo = tid * 4;
    float wl[4], wr[4];
    #pragma unroll
    for (int t = 0; t < 4; t++) {
        wl[t] = srow[xo + t];            // left taps, slides forward
        wr[t] = srow[xo + n - 1 + t];    // right taps, slides backward
    }
    float hi[4] = {2.f, 2.f, 2.f, 2.f};
    float lo[4] = {0.f, 0.f, 0.f, 0.f};

    #pragma unroll 4
    for (int j = 0; j < r; j++) {
        float k = sk[j];
        #pragma unroll
        for (int t = 0; t < 4; t++) {
            float s  = __fadd_rn(wl[t], wr[t]);
            float p  = __fmul_rn(s, k);
            float ep = __fmaf_rn(s, k, -p);       // exact product residual
            float t2 = __fadd_rn(hi[t], p);       // Fast2Sum (hi >= 2 > p)
            float e  = __fsub_rn(p, __fsub_rn(t2, hi[t]));
            hi[t] = t2;
            lo[t] = __fadd_rn(lo[t], e);
            lo[t] = __fadd_rn(lo[t], ep);
        }
        wl[0] = wl[1]; wl[1] = wl[2]; wl[2] = wl[3];
        wl[3] = srow[xo + j + 4];
        wr[3] = wr[2]; wr[2] = wr[1]; wr[1] = wr[0];
        wr[0] = srow[xo + n - 2 - j];
    }
    // center tap: wl[t] == srow[xo + r + t] after r slides
    {
        float kc = sk[r];
        #pragma unroll
        for (int t = 0; t < 4; t++) {
            float a  = wl[t];
            float p  = __fmul_rn(a, kc);
            float ep = __fmaf_rn(a, kc, -p);
            float t2 = __fadd_rn(hi[t], p);
            float e  = __fsub_rn(p, __fsub_rn(t2, hi[t]));
            hi[t] = t2;
            lo[t] = __fadd_rn(lo[t], e);
            lo[t] = __fadd_rn(lo[t], ep);
        }
    }
    float2* outp = d_tmp + (size_t)(sc*H + y) * W + xo;
    #pragma unroll
    for (int t = 0; t < 4; t++)
        outp[t] = make_float2(__fsub_rn(hi[t], 2.f), lo[t]);
}

// ---------------------------------------------------------------
// Vertical pass, symmetric pairing on df64 inputs.
// 32-wide x-strip, 32 output rows/block, 4 per thread.
// blockDim (32,8), grid (16,16,NS).
// ---------------------------------------------------------------
#define VTX 32
#define VTY 32
__global__ void vblur_k() {
    int sc = blockIdx.z;
    int x0 = blockIdx.x * VTX;
    int y0 = blockIdx.y * VTY;
    int r  = d_rad[sc];
    int n  = 2 * r + 1;
    __shared__ float2 tile[(VTY + 2*MAXR + 4) * VTX];
    __shared__ float  sk[96];
    int tx  = threadIdx.x;
    int tid = tx + threadIdx.y * VTX;   // 256 threads
    int rows = VTY + 2 * r + 3;
    const float2* inp = d_tmp + (size_t)sc * H * W;
    for (int i = tid; i < rows * VTX; i += 256) {
        int rr = i / VTX, cc = i % VTX;
        int gy = y0 - r + rr;
        tile[i] = (gy >= 0 && gy < H) ? inp[gy*W + x0 + cc] : make_float2(0.f, 0.f);
    }
    for (int i = tid; i < n; i += 256) sk[i] = d_kx[sc*96 + i];
    __syncthreads();

    int yo = threadIdx.y * 4;
    float2 wl[4], wr[4];
    #pragma unroll
    for (int t = 0; t < 4; t++) {
        wl[t] = tile[(yo + t)*VTX + tx];
        wr[t] = tile[(yo + n - 1 + t)*VTX + tx];
    }
    float hi[4] = {2.f, 2.f, 2.f, 2.f};
    float lo[4] = {0.f, 0.f, 0.f, 0.f};

    #pragma unroll 4
    for (int j = 0; j < r; j++) {
        float k = sk[j];
        #pragma unroll
        for (int t = 0; t < 4; t++) {
            float sx = __fadd_rn(wl[t].x, wr[t].x);
            float sy = __fadd_rn(wl[t].y, wr[t].y);
            float p  = __fmul_rn(sx, k);
            float ep = __fmaf_rn(sx, k, -p);
            ep = __fmaf_rn(sy, k, ep);
            float t2 = __fadd_rn(hi[t], p);
            float e  = __fsub_rn(p, __fsub_rn(t2, hi[t]));
            hi[t] = t2;
            lo[t] = __fadd_rn(lo[t], e);
            lo[t] = __fadd_rn(lo[t], ep);
        }
        wl[0] = wl[1]; wl[1] = wl[2]; wl[2] = wl[3];
        wl[3] = tile[(yo + j + 4)*VTX + tx];
        wr[3] = wr[2]; wr[2] = wr[1]; wr[1] = wr[0];
        wr[0] = tile[(yo + n - 2 - j)*VTX + tx];
    }
    // center tap
    {
        float kc = sk[r];
        #pragma unroll
        for (int t = 0; t < 4; t++) {
            float2 a = wl[t];
            float p  = __fmul_rn(a.x, kc);
            float ep = __fmaf_rn(a.x, kc, -p);
            ep = __fmaf_rn(a.y, kc, ep);
            float t2 = __fadd_rn(hi[t], p);
            float e  = __fsub_rn(p, __fsub_rn(t2, hi[t]));
            hi[t] = t2;
            lo[t] = __fadd_rn(lo[t], e);
            lo[t] = __fadd_rn(lo[t], ep);
        }
    }
    float* outp = d_g + (size_t)sc * H * W;
    #pragma unroll
    for (int t = 0; t < 4; t++)
        outp[(y0 + yo + t)*W + x0 + tx] =
            __fadd_rn(__fsub_rn(hi[t], 2.f), lo[t]);
}

// ---------------------------------------------------------------
// FUSED DoG + peak, separable max-pool formulation.
// pk = (c > THRESH) && (c >= max27) where max27 includes c
//    == reference's (dog == maxpool3^3) & (dog > thr).  Exact.
// Per cell: load 4 g values once -> 3 dog planes -> zmax (cross-k),
// store zmax + center dog. Then vertical max3, then horizontal
// max3 + compare. Div-free 2D indexing.
// blockDim (32,8), grid (4, 64, NK-2).
// ---------------------------------------------------------------
#define PTX 128
#define PTY 8
#define TCOLS (PTX + 2)
__global__ void peak_k() {
    int k  = blockIdx.z + 1;            // 1..11
    int y0 = blockIdx.y * PTY;
    int x0 = blockIdx.x * PTX;
    __shared__ float szmax[PTY + 2][TCOLS];
    __shared__ float sdogc[PTY + 2][TCOLS];
    __shared__ float svmax[PTY][TCOLS];
    int tx = threadIdx.x;
    int ty = threadIdx.y;

    float sgm1 = d_sig[k-1], sg0 = d_sig[k], sgp1 = d_sig[k+1];
    const float* gm1 = d_g + (size_t)(k-1) * H * W;
    const float* g0  = gm1 + H * W;
    const float* gp1 = g0  + H * W;
    const float* gp2 = gp1 + H * W;

    // fill: dog for 3 planes from 4 g loads; zmax + center dog stored
    #pragma unroll
    for (int rr = ty; rr < PTY + 2; rr += 8) {
        int gy = y0 - 1 + rr; if (gy < 0) gy = 0; if (gy > H-1) gy = H-1;
        int gyW = gy * W;
        #pragma unroll
        for (int cc = tx; cc < TCOLS; cc += 32) {
            int gx = x0 - 1 + cc; if (gx > W-1) gx = W-1;  // cc>=0 => gx>=-1
            if (gx < 0) gx = 0;
            int gi = gyW + gx;
            float a = gm1[gi], b = g0[gi], c = gp1[gi], d = gp2[gi];
            float dm1 = (a - b) * sgm1;
            float dc  = (b - c) * sg0;
            float dp1 = (c - d) * sgp1;
            szmax[rr][cc] = fmaxf(fmaxf(dm1, dc), dp1);
            sdogc[rr][cc] = dc;
        }
    }
    __syncthreads();

    // vertical max3: row ty covers output row y0+ty (tile row ty+1)
    #pragma unroll
    for (int cc = tx; cc < TCOLS; cc += 32)
        svmax[ty][cc] = fmaxf(fmaxf(szmax[ty][cc], szmax[ty+1][cc]),
                              szmax[ty+2][cc]);
    __syncthreads();

    // horizontal max3 + compare
    int y = y0 + ty;
    #pragma unroll
    for (int q = 0; q < 4; q++) {
        int x  = x0 + q * 32 + tx;
        int lx = q * 32 + tx + 1;
        bool pk = false;
        if (y >= 1 && y <= H-2 && x >= 1 && x <= W-2) {
            float c = sdogc[ty+1][lx];
            if (c > THRESH) {
                float m = fmaxf(fmaxf(svmax[ty][lx-1], svmax[ty][lx]),
                                svmax[ty][lx+1]);
                pk = (c >= m);
            }
        }
        unsigned wmask = __ballot_sync(0xFFFFFFFFu, pk);
        if (tx == 0) d_maskw[(k*H + y)*16 + (x0/32 + q)] = wmask;
    }
}

// ---------------------------------------------------------------
// Fused count+scan over 6656 rows (row-major order), single block.
// ---------------------------------------------------------------
__global__ void scan_k() {
    const int PER = (NROWS + 1023) / 1024;   // 7
    int tid = threadIdx.x;
    int vals[PER];
    int local = 0;
    int start = tid * PER;
    #pragma unroll
    for (int j = 0; j < PER; j++) {
        int idx = start + j;
        int v = 0;
        if (idx < NROWS) {
            const uint4* mw = (const uint4*)(d_maskw + idx*16);
            #pragma unroll
            for (int q = 0; q < 4; q++) {
                uint4 m = mw[q];
                v += __popc(m.x) + __popc(m.y) + __popc(m.z) + __popc(m.w);
            }
        }
        vals[j] = v;
        local += v;
    }
    __shared__ int sh[1024];
    sh[tid] = local;
    __syncthreads();
    for (int off = 1; off < 1024; off <<= 1) {
        int v = (tid >= off) ? sh[tid - off] : 0;
        __syncthreads();
        sh[tid] += v;
        __syncthreads();
    }
    int run = sh[tid] - local;
    #pragma unroll
    for (int j = 0; j < PER; j++) {
        int idx = start + j;
        if (idx < NROWS) { d_rowcnt[idx] = run; run += vals[j]; }
    }
    if (tid == 1023) d_total = sh[1023];
}

// ---------------------------------------------------------------
// Fused fill + scatter (disjoint index ranges, order-independent).
// grid NROWS blocks of 32 threads.
// ---------------------------------------------------------------
__global__ void write_k(float* __restrict__ out) {
    int rid  = blockIdx.x;
    int lane = threadIdx.x;
    int total = d_total;
    float sig0 = d_sig[0];
    #pragma unroll
    for (int j = 0; j < 5; j++) {          // 5*NROWS = 33280 >= MAXPEAKS
        int f = rid + j * NROWS;
        if (f < MAXPEAKS && f >= total && lane < 3)
            out[3*f + lane] = (lane == 0) ? sig0 : 0.f;
    }
    int k = rid >> 9, y = rid & 511;
    int run = d_rowcnt[rid];
    float sg = d_sig[k];
    for (int w = 0; w < 16; w++) {
        unsigned word = d_maskw[rid*16 + w];
        if (word) {
            if ((word >> lane) & 1u) {
                int idx = run + __popc(word & ((1u << lane) - 1u));
                if (idx < MAXPEAKS) {
                    out[3*idx]     = sg;
                    out[3*idx + 1] = (float)y;
                    out[3*idx + 2] = (float)(w*32 + lane);
                }
            }
            run += __popc(word);
        }
    }
}

extern "C" void kernel_launch(void* const* d_in, const int* in_sizes, int n_in,
                              void* d_out, int out_size) {
    const float* x     = nullptr;
    const float* sigma = nullptr;
    for (int i = 0; i < n_in; i++) {
        if (in_sizes[i] == H * W)   x     = (const float*)d_in[i];
        else if (in_sizes[i] == NS) sigma = (const float*)d_in[i];
    }
    if (!x)     x     = (const float*)d_in[0];
    if (!sigma) sigma = (const float*)d_in[n_in - 1];

    float* out = (float*)d_out;                   // [32768, 3]

    build_kernels_k<<<NS, 128>>>(sigma);
    hblur_k<<<dim3(H, NS), 128>>>(x);
    vblur_k<<<dim3(W/VTX, H/VTY, NS), dim3(VTX, 8)>>>();
    peak_k<<<dim3(W/PTX, H/PTY, NK-2), dim3(32, 8)>>>();
    scan_k<<<1, 1024>>>();
    write_k<<<NROWS, 32>>>(out);
}